// round 15
// baseline (speedup 1.0000x reference)
#include <cuda_runtime.h>
#include <cuda_bf16.h>
#include <cuda_fp16.h>
#include <cstdint>

// Problem constants
#define B_      32
#define C_      256
#define HW_     1024
#define NTOK    32768
#define KCODES  1024
#define BETA    0.25f

// Output layout (concatenated float32): u, z_train, vq_loss, indices
#define SZ_U    8388608
#define OFF_U   0
#define OFF_ZT  8388608
#define OFF_LOSS 16777216
#define OFF_IDX  16777217

// GEMM tiling: CTA = 64 codes (MMA-M) x 256 tokens (MMA-N), K=256 in 8x32
#define TOKT 256
#define CODT 64
#define NTILE (KCODES / CODT)   // 16
#define SAU_H 264       // u16 smem stride (halves)
#define SAC_H 40        // cb16 smem stride (halves)
#define GEMM_SMEM (2 * 32 * SAU_H * 2 + 2 * CODT * SAC_H * 2)   // 44032 B

// Device scratch
__device__ float g_codebookT[C_ * KCODES];     // [c][code]
__device__ float g_cnorm[KCODES];
__device__ unsigned g_cmax_bits;
__device__ float g_unorm[NTOK];
__device__ int   g_idx[NTOK];
__device__ float g_partial[B_ * C_];
__device__ __align__(16) __half g_u16[NTOK * C_];    // [b][c][hw] f16, 16 MB
__device__ __align__(16) __half g_cb16[KCODES * C_]; // [code][k] f16
__device__ __align__(16) float4 g_sum[NTOK * NTILE]; // {m1, m2, idx_bits, pad}
__device__ int   g_nambig;
__device__ int   g_ambig[NTOK];
__device__ float g_lim[NTOK];

// ---------------------------------------------------------------------------
__device__ __forceinline__ uint32_t pack_f16x2(float hi, float lo) {
    uint32_t d;
    asm("cvt.rn.f16x2.f32 %0, %1, %2;" : "=r"(d) : "f"(hi), "f"(lo));
    return d;
}

#define CPA16(dst, src) \
    asm volatile("cp.async.cg.shared.global [%0], [%1], 16;" :: "r"(dst), "l"(src))
#define CPA_COMMIT() asm volatile("cp.async.commit_group;" ::: "memory")
#define CPA_WAIT0()  asm volatile("cp.async.wait_group 0;" ::: "memory")

__device__ __forceinline__ void ldsm_x4(uint32_t* r, uint32_t a) {
    asm volatile("ldmatrix.sync.aligned.m8n8.x4.shared.b16 {%0,%1,%2,%3}, [%4];"
        : "=r"(r[0]), "=r"(r[1]), "=r"(r[2]), "=r"(r[3]) : "r"(a));
}
__device__ __forceinline__ void ldsm_x2t(uint32_t* r, uint32_t a) {
    asm volatile("ldmatrix.sync.aligned.m8n8.x2.trans.shared.b16 {%0,%1}, [%2];"
        : "=r"(r[0]), "=r"(r[1]) : "r"(a));
}

__device__ __forceinline__ void mma_f16(float* c, const uint32_t* a,
                                        const uint32_t* b) {
    asm volatile(
        "mma.sync.aligned.m16n8k16.row.col.f32.f16.f16.f32 "
        "{%0,%1,%2,%3}, {%4,%5,%6,%7}, {%8,%9}, {%0,%1,%2,%3};"
        : "+f"(c[0]), "+f"(c[1]), "+f"(c[2]), "+f"(c[3])
        : "r"(a[0]), "r"(a[1]), "r"(a[2]), "r"(a[3]), "r"(b[0]), "r"(b[1]));
}

__device__ __forceinline__ void upd_min2(float v, int i, float& m1, int& i1,
                                         float& m2) {
    if (v < m1) { m2 = m1; m1 = v; i1 = i; }
    else if (v < m2) { m2 = v; }
}

__device__ __forceinline__ void merge_min2(float& v1, int& i1, float& v2,
                                           float ov1, int oi1, float ov2) {
    if (ov1 < v1 || (ov1 == v1 && oi1 < i1)) {
        v2 = fminf(v1, ov2);
        v1 = ov1; i1 = oi1;
    } else {
        v2 = fminf(v2, ov1);
    }
}

// ---------------------------------------------------------------------------
// K0: codebook transpose + |c|^2 + cmax + f16 copy + zero ambig counter
// ---------------------------------------------------------------------------
__global__ void __launch_bounds__(256) prep_kernel(const float* __restrict__ cb) {
    __shared__ float s[256];
    int k = blockIdx.x;
    int c = threadIdx.x;
    if (k == 0 && c == 0) g_nambig = 0;
    float v = cb[k * C_ + c];
    g_codebookT[c * KCODES + k] = v;
    g_cb16[k * C_ + c] = __float2half_rn(v);
    s[c] = v * v;
    __syncthreads();
    #pragma unroll
    for (int stride = 128; stride > 0; stride >>= 1) {
        if (c < stride) s[c] += s[c + stride];
        __syncthreads();
    }
    if (c == 0) {
        g_cnorm[k] = s[0];
        atomicMax(&g_cmax_bits, __float_as_uint(s[0]));
    }
}

// K0b: per-token ||u|| (runs on side stream, overlapped with gemm)
__global__ void __launch_bounds__(128) unorm_kernel(const float* __restrict__ u) {
    const int b = blockIdx.y;
    const int hw = blockIdx.x * 128 + threadIdx.x;
    const float* up = u + (size_t)b * (C_ * HW_) + hw;
    float acc = 0.f;
    #pragma unroll 8
    for (int c = 0; c < C_; ++c) {
        float v = up[c * HW_];
        acc = fmaf(v, v, acc);
    }
    g_unorm[(b << 10) + hw] = sqrtf(acc) * 1.0002f;
}

// K0c: u -> f16. 1024 blocks x 256 thr x 8 float4.
__global__ void __launch_bounds__(256) prep_u16_kernel(const float* __restrict__ u) {
    const float4* u4 = (const float4*)u;
    uint2* h4 = (uint2*)g_u16;
    const size_t base = (size_t)blockIdx.x * 2048 + (size_t)threadIdx.x * 8;
    #pragma unroll
    for (int p = 0; p < 8; ++p) {
        float4 v = u4[base + p];
        uint2 wv;
        wv.x = pack_f16x2(v.y, v.x);
        wv.y = pack_f16x2(v.w, v.z);
        h4[base + p] = wv;
    }
}

// K0d: out_u = u (side stream, overlapped with gemm)
__global__ void __launch_bounds__(256) copy_u_kernel(const float4* __restrict__ u4,
                                                     float4* __restrict__ o4) {
    const size_t base = (size_t)blockIdx.x * 2048 + (size_t)threadIdx.x * 8;
    #pragma unroll
    for (int p = 0; p < 8; ++p) o4[base + p] = u4[base + p];
}

// ---------------------------------------------------------------------------
// K1: fp16 GEMM, all-f16 smem, cp.async double buffer, ldmatrix operands,
// fused per-tile argmin over codes. grid (16, 128), 256 threads (8 warps).
// ---------------------------------------------------------------------------
__global__ void __launch_bounds__(256, 2) gemm_kernel() {
    extern __shared__ __half smh[];
    __half* Ubuf = smh;                         // [2][32*SAU_H]
    __half* Abuf = smh + 2 * 32 * SAU_H;        // [2][CODT*SAC_H]

    const int tid = threadIdx.x;
    const int w = tid >> 5, lane = tid & 31;
    const int g = lane >> 2, q = lane & 3;
    const int code0 = blockIdx.x * CODT;
    const int tok0 = blockIdx.y * TOKT;
    const int b = tok0 >> 10, hw0 = tok0 & 1023;
    const __half* ub16 = g_u16 + (size_t)b * (C_ * HW_) + hw0;
    const __half* cb16 = g_cb16 + (size_t)code0 * C_;

    float acc[4][4][4];
    #pragma unroll
    for (int mt = 0; mt < 4; ++mt)
        #pragma unroll
        for (int nt = 0; nt < 4; ++nt)
            #pragma unroll
            for (int e = 0; e < 4; ++e) acc[mt][nt][e] = 0.f;

    const int a_row = lane & 15, a_col = (lane >> 4) << 3;
    const int b_k = lane & 15;

    #define STAGE_U16(kc, buf) do {                                            \
        __half* Ub_ = Ubuf + (buf) * (32 * SAU_H);                              \
        const int k0_ = (kc) * 32;                                              \
        _Pragma("unroll")                                                       \
        for (int p = 0; p < 4; ++p) {                                           \
            int id = tid + p * 256;                                             \
            int kr = id >> 5, cq = id & 31;                                     \
            uint32_t dst = (uint32_t)__cvta_generic_to_shared(                  \
                Ub_ + kr * SAU_H + cq * 8);                                     \
            CPA16(dst, ub16 + (size_t)(k0_ + kr) * HW_ + cq * 8);               \
        }                                                                       \
    } while (0)
    #define STAGE_CB16(kc, buf) do {                                            \
        __half* Ab_ = Abuf + (buf) * (CODT * SAC_H);                             \
        const int k0_ = (kc) * 32;                                               \
        int row = tid >> 2, cq = tid & 3;                                        \
        uint32_t dst = (uint32_t)__cvta_generic_to_shared(                       \
            Ab_ + row * SAC_H + cq * 8);                                         \
        CPA16(dst, cb16 + (size_t)row * C_ + k0_ + cq * 8);                      \
    } while (0)

    STAGE_U16(0, 0);
    STAGE_CB16(0, 0);
    CPA_COMMIT();
    CPA_WAIT0();
    __syncthreads();

    for (int kc = 0; kc < 8; ++kc) {
        const int buf = kc & 1;
        if (kc < 7) {
            STAGE_U16(kc + 1, buf ^ 1);
            STAGE_CB16(kc + 1, buf ^ 1);
            CPA_COMMIT();
        }

        const __half* Ub = Ubuf + buf * (32 * SAU_H);
        const __half* Ab = Abuf + buf * (CODT * SAC_H);
        const int n0 = w * 32;

        #pragma unroll
        for (int ks = 0; ks < 2; ++ks) {
            const int kb = ks * 16;
            uint32_t bf[4][2];
            #pragma unroll
            for (int nt = 0; nt < 4; ++nt) {
                uint32_t a = (uint32_t)__cvta_generic_to_shared(
                    Ub + (kb + b_k) * SAU_H + n0 + nt * 8);
                ldsm_x2t(bf[nt], a);
            }
            uint32_t af[4][4];
            #pragma unroll
            for (int mt = 0; mt < 4; ++mt) {
                uint32_t a = (uint32_t)__cvta_generic_to_shared(
                    Ab + (mt * 16 + a_row) * SAC_H + kb + a_col);
                ldsm_x4(af[mt], a);
            }
            #pragma unroll
            for (int mt = 0; mt < 4; ++mt)
                #pragma unroll
                for (int nt = 0; nt < 4; ++nt)
                    mma_f16(acc[mt][nt], af[mt], bf[nt]);
        }
        if (kc < 7) CPA_WAIT0();
        __syncthreads();
    }

    // fused argmin over codes (M)
    #pragma unroll
    for (int nt = 0; nt < 4; ++nt) {
        #pragma unroll
        for (int e = 0; e < 2; ++e) {
            float m1 = 3.4e38f, m2 = 3.4e38f;
            int i1 = 0;
            #pragma unroll
            for (int mt = 0; mt < 4; ++mt) {
                const int clo = code0 + mt * 16 + g;
                upd_min2(fmaf(-2.f, acc[mt][nt][e], __ldg(&g_cnorm[clo])),
                         clo, m1, i1, m2);
                upd_min2(fmaf(-2.f, acc[mt][nt][2 + e], __ldg(&g_cnorm[clo + 8])),
                         clo + 8, m1, i1, m2);
            }
            #pragma unroll
            for (int off = 4; off <= 16; off <<= 1) {
                float ov1 = __shfl_xor_sync(0xffffffffu, m1, off);
                int   oi1 = __shfl_xor_sync(0xffffffffu, i1, off);
                float ov2 = __shfl_xor_sync(0xffffffffu, m2, off);
                merge_min2(m1, i1, m2, ov1, oi1, ov2);
            }
            if (g == 0) {
                const int tok = tok0 + w * 32 + nt * 8 + 2 * q + e;
                g_sum[(size_t)tok * NTILE + blockIdx.x] =
                    make_float4(m1, m2, __int_as_float(i1), 0.f);
            }
        }
    }
}

// ---------------------------------------------------------------------------
// K2: reduce. Thread per token; 16 contiguous float4 summary reads.
// ---------------------------------------------------------------------------
__global__ void __launch_bounds__(256) reduce_kernel(float* __restrict__ out_idx) {
    const int tok = blockIdx.x * 256 + threadIdx.x;
    const float4* sp = g_sum + (size_t)tok * NTILE;
    float m1 = 3.4e38f, m2 = 3.4e38f;
    int i1 = 0;
    #pragma unroll
    for (int t = 0; t < NTILE; ++t) {
        float4 s = sp[t];
        merge_min2(m1, i1, m2, s.x, __float_as_int(s.z), s.y);
    }
    g_idx[tok] = i1;
    out_idx[tok] = (float)i1;
    const float cmax = sqrtf(__uint_as_float(g_cmax_bits)) * 1.0002f;
    const float margin = g_unorm[tok] * cmax * (1.02f / 512.f) + 2e-3f;
    if (m2 - m1 <= margin) {
        int slot = atomicAdd(&g_nambig, 1);
        g_ambig[slot] = tok;
        g_lim[slot] = m1 + margin;
    }
}

// ---------------------------------------------------------------------------
// K3: worklist rescue. Warp per entry; float4-coalesced exact fp32 dots.
// ---------------------------------------------------------------------------
__global__ void __launch_bounds__(256) rescue_kernel(const float* __restrict__ u,
                                                     const float* __restrict__ cb,
                                                     float* __restrict__ out_idx) {
    __shared__ __align__(16) float us[8][C_];
    const int wid = threadIdx.x >> 5, lane = threadIdx.x & 31;
    const int gw = blockIdx.x * 8 + wid;
    const int nwarps = gridDim.x * 8;
    const int n = g_nambig;

    const int group = lane >> 3;
    const int ks = (lane & 7) << 2;

    for (int i = gw; i < n; i += nwarps) {
        const int tok = g_ambig[i];
        const float lim = g_lim[i];
        const int b = tok >> 10, hw = tok & 1023;
        #pragma unroll
        for (int r = 0; r < 8; ++r) {
            int c = lane + r * 32;
            us[wid][c] = u[((size_t)(b * C_ + c) << 10) + hw];
        }
        __syncwarp();
        float4 uu[8];
        #pragma unroll
        for (int r = 0; r < 8; ++r)
            uu[r] = *(const float4*)&us[wid][ks + r * 32];

        const float4* sp = g_sum + (size_t)tok * NTILE;
        float best = 3.4e38f;
        int bi = KCODES;
        for (int t = 0; t < NTILE; ++t) {
            if (sp[t].x > lim) continue;
            const int cb0 = t * CODT;
            #pragma unroll 4
            for (int p = 0; p < 16; ++p) {
                const int cg = cb0 + p * 4 + group;
                const float* cp = cb + (size_t)cg * C_ + ks;
                float d = 0.f;
                #pragma unroll
                for (int r = 0; r < 8; ++r) {
                    float4 x = *(const float4*)&cp[r * 32];
                    d = fmaf(x.x, uu[r].x, d);
                    d = fmaf(x.y, uu[r].y, d);
                    d = fmaf(x.z, uu[r].z, d);
                    d = fmaf(x.w, uu[r].w, d);
                }
                d += __shfl_xor_sync(0xffffffffu, d, 1);
                d += __shfl_xor_sync(0xffffffffu, d, 2);
                d += __shfl_xor_sync(0xffffffffu, d, 4);
                const float s = fmaf(-2.f, d, __ldg(&g_cnorm[cg]));
                if (s < best || (s == best && cg < bi)) { best = s; bi = cg; }
            }
        }
        #pragma unroll
        for (int off = 16; off > 0; off >>= 1) {
            float ov = __shfl_xor_sync(0xffffffffu, best, off);
            int oi = __shfl_xor_sync(0xffffffffu, bi, off);
            if (ov < best || (ov == best && oi < bi)) { best = ov; bi = oi; }
        }
        if (lane == 0) {
            g_idx[tok] = bi;
            out_idx[tok] = (float)bi;
        }
        __syncwarp();
    }
}

// ---------------------------------------------------------------------------
// K4: outputs. gather z_q, write z_train, accumulate (z_q - u)^2 per (b,c).
// (u copy moved to copy_u_kernel on the side stream.)
// ---------------------------------------------------------------------------
__global__ void __launch_bounds__(256) epilogue_kernel(const float* __restrict__ u,
                                                       float* __restrict__ out) {
    __shared__ float col[KCODES];
    __shared__ float sred[256];
    const int c = blockIdx.x;
    const int b = blockIdx.y;
    const int tid = threadIdx.x;

    ((float4*)col)[tid] = ((const float4*)(g_codebookT + c * KCODES))[tid];
    __syncthreads();

    const long base = ((long)(b * C_ + c)) << 10;
    const float* ub = u + base;
    float* oz = out + OFF_ZT + base;
    const int* ib = g_idx + (b << 10);

    float acc = 0.f;
    #pragma unroll
    for (int j = 0; j < 4; ++j) {
        int hw = tid + (j << 8);
        int i = ib[hw];
        float z = col[i];
        float uu = ub[hw];
        oz[hw] = z;
        float d = z - uu;
        acc = fmaf(d, d, acc);
    }
    sred[tid] = acc;
    __syncthreads();
    #pragma unroll
    for (int stride = 128; stride > 0; stride >>= 1) {
        if (tid < stride) sred[tid] += sred[tid + stride];
        __syncthreads();
    }
    if (tid == 0) g_partial[b * C_ + c] = sred[0];
}

// ---------------------------------------------------------------------------
// K5: final loss
// ---------------------------------------------------------------------------
__global__ void __launch_bounds__(256) loss_kernel(float* __restrict__ out) {
    __shared__ float s[256];
    const int tid = threadIdx.x;
    float a = 0.f;
    for (int i = tid; i < B_ * C_; i += 256) a += g_partial[i];
    s[tid] = a;
    __syncthreads();
    #pragma unroll
    for (int stride = 128; stride > 0; stride >>= 1) {
        if (tid < stride) s[tid] += s[tid + stride];
        __syncthreads();
    }
    if (tid == 0)
        out[OFF_LOSS] = s[0] * (1.0f + BETA) / (float)SZ_U;
}

// ---------------------------------------------------------------------------
extern "C" void kernel_launch(void* const* d_in, const int* in_sizes, int n_in,
                              void* d_out, int out_size) {
    const float* u  = (const float*)d_in[0];
    const float* cb = (const float*)d_in[1];
    float* out = (float*)d_out;

    static cudaStream_t s2 = nullptr;
    static cudaEvent_t ev_fork = nullptr, ev_join = nullptr;
    if (!s2) {
        cudaFuncSetAttribute(gemm_kernel,
                             cudaFuncAttributeMaxDynamicSharedMemorySize,
                             GEMM_SMEM);
        cudaStreamCreateWithFlags(&s2, cudaStreamNonBlocking);
        cudaEventCreateWithFlags(&ev_fork, cudaEventDisableTiming);
        cudaEventCreateWithFlags(&ev_join, cudaEventDisableTiming);
    }

    // fork side stream off the capture stream
    cudaEventRecord(ev_fork, 0);
    cudaStreamWaitEvent(s2, ev_fork, 0);

    // side stream: work independent of the gemm (overlaps with it)
    unorm_kernel<<<dim3(8, B_), 128, 0, s2>>>(u);
    copy_u_kernel<<<1024, 256, 0, s2>>>((const float4*)u, (float4*)(out + OFF_U));
    cudaEventRecord(ev_join, s2);

    // main stream
    prep_kernel<<<KCODES, 256>>>(cb);
    prep_u16_kernel<<<1024, 256>>>(u);
    gemm_kernel<<<dim3(NTILE, NTOK / TOKT), 256, GEMM_SMEM>>>();

    // join: reduce needs g_unorm
    cudaStreamWaitEvent(0, ev_join, 0);
    reduce_kernel<<<NTOK / 256, 256>>>(out + OFF_IDX);
    rescue_kernel<<<512, 256>>>(u, cb, out + OFF_IDX);
    epilogue_kernel<<<dim3(C_, B_), 256>>>(u, out);
    loss_kernel<<<1, 256>>>(out);
}

// round 16
// speedup vs baseline: 1.0615x; 1.0615x over previous
#include <cuda_runtime.h>
#include <cuda_bf16.h>
#include <cuda_fp16.h>
#include <cstdint>

// Problem constants
#define B_      32
#define C_      256
#define HW_     1024
#define NTOK    32768
#define KCODES  1024
#define BETA    0.25f

// Output layout (concatenated float32): u, z_train, vq_loss, indices
#define SZ_U    8388608
#define OFF_U   0
#define OFF_ZT  8388608
#define OFF_LOSS 16777216
#define OFF_IDX  16777217

// GEMM tiling: CTA = 64 codes (MMA-M) x 256 tokens (MMA-N), K=256 in 8x32
#define TOKT 256
#define CODT 64
#define NTILE (KCODES / CODT)   // 16
#define SAU_H 264       // u16 smem stride (halves)
#define SAC_H 40        // cb16 smem stride (halves)
#define GEMM_SMEM (2 * 32 * SAU_H * 2 + 2 * CODT * SAC_H * 2)   // 44032 B

// Device scratch
__device__ float g_codebookT[C_ * KCODES];     // [c][code]
__device__ float g_cnorm[KCODES];
__device__ unsigned g_cmax_bits;
__device__ float g_unorm[NTOK];
__device__ int   g_idx[NTOK];
__device__ float g_partial[B_ * C_];
__device__ __align__(16) __half g_u16[NTOK * C_];    // [b][c][hw] f16, 16 MB
__device__ __align__(16) __half g_cb16[KCODES * C_]; // [code][k] f16
__device__ __align__(16) float4 g_sum[NTOK * NTILE]; // {m1, m2, idx_bits, pad}
__device__ int   g_nambig;
__device__ int   g_ambig[NTOK];
__device__ float g_lim[NTOK];

// ---------------------------------------------------------------------------
__device__ __forceinline__ uint32_t pack_f16x2(float hi, float lo) {
    uint32_t d;
    asm("cvt.rn.f16x2.f32 %0, %1, %2;" : "=r"(d) : "f"(hi), "f"(lo));
    return d;
}

#define CPA16(dst, src) \
    asm volatile("cp.async.cg.shared.global [%0], [%1], 16;" :: "r"(dst), "l"(src))
#define CPA_COMMIT() asm volatile("cp.async.commit_group;" ::: "memory")
#define CPA_WAIT0()  asm volatile("cp.async.wait_group 0;" ::: "memory")

__device__ __forceinline__ void ldsm_x4(uint32_t* r, uint32_t a) {
    asm volatile("ldmatrix.sync.aligned.m8n8.x4.shared.b16 {%0,%1,%2,%3}, [%4];"
        : "=r"(r[0]), "=r"(r[1]), "=r"(r[2]), "=r"(r[3]) : "r"(a));
}
__device__ __forceinline__ void ldsm_x2t(uint32_t* r, uint32_t a) {
    asm volatile("ldmatrix.sync.aligned.m8n8.x2.trans.shared.b16 {%0,%1}, [%2];"
        : "=r"(r[0]), "=r"(r[1]) : "r"(a));
}

__device__ __forceinline__ void mma_f16(float* c, const uint32_t* a,
                                        const uint32_t* b) {
    asm volatile(
        "mma.sync.aligned.m16n8k16.row.col.f32.f16.f16.f32 "
        "{%0,%1,%2,%3}, {%4,%5,%6,%7}, {%8,%9}, {%0,%1,%2,%3};"
        : "+f"(c[0]), "+f"(c[1]), "+f"(c[2]), "+f"(c[3])
        : "r"(a[0]), "r"(a[1]), "r"(a[2]), "r"(a[3]), "r"(b[0]), "r"(b[1]));
}

__device__ __forceinline__ void upd_min2(float v, int i, float& m1, int& i1,
                                         float& m2) {
    if (v < m1) { m2 = m1; m1 = v; i1 = i; }
    else if (v < m2) { m2 = v; }
}

__device__ __forceinline__ void merge_min2(float& v1, int& i1, float& v2,
                                           float ov1, int oi1, float ov2) {
    if (ov1 < v1 || (ov1 == v1 && oi1 < i1)) {
        v2 = fminf(v1, ov2);
        v1 = ov1; i1 = oi1;
    } else {
        v2 = fminf(v2, ov1);
    }
}

// ---------------------------------------------------------------------------
// K0: codebook transpose + |c|^2 + cmax + f16 copy + zero ambig counter
// ---------------------------------------------------------------------------
__global__ void __launch_bounds__(256) prep_kernel(const float* __restrict__ cb) {
    __shared__ float s[256];
    int k = blockIdx.x;
    int c = threadIdx.x;
    if (k == 0 && c == 0) g_nambig = 0;
    float v = cb[k * C_ + c];
    g_codebookT[c * KCODES + k] = v;
    g_cb16[k * C_ + c] = __float2half_rn(v);
    s[c] = v * v;
    __syncthreads();
    #pragma unroll
    for (int stride = 128; stride > 0; stride >>= 1) {
        if (c < stride) s[c] += s[c + stride];
        __syncthreads();
    }
    if (c == 0) {
        g_cnorm[k] = s[0];
        atomicMax(&g_cmax_bits, __float_as_uint(s[0]));
    }
}

// K0b: per-token ||u|| (fp32, exact)
__global__ void __launch_bounds__(128) unorm_kernel(const float* __restrict__ u) {
    const int b = blockIdx.y;
    const int hw = blockIdx.x * 128 + threadIdx.x;
    const float* up = u + (size_t)b * (C_ * HW_) + hw;
    float acc = 0.f;
    #pragma unroll 8
    for (int c = 0; c < C_; ++c) {
        float v = up[c * HW_];
        acc = fmaf(v, v, acc);
    }
    g_unorm[(b << 10) + hw] = sqrtf(acc) * 1.0002f;
}

// K0c: u -> f16, coalesced (consecutive threads -> consecutive float4s).
// 1024 blocks x 8 passes x 256 float4 = 8,388,608 floats exactly.
__global__ void __launch_bounds__(256) prep_u16_kernel(const float* __restrict__ u) {
    const float4* u4 = (const float4*)u;
    uint2* h4 = (uint2*)g_u16;
    const size_t base = (size_t)blockIdx.x * 2048 + threadIdx.x;
    #pragma unroll
    for (int p = 0; p < 8; ++p) {
        const size_t idx = base + p * 256;
        float4 v = u4[idx];
        uint2 wv;
        wv.x = pack_f16x2(v.y, v.x);
        wv.y = pack_f16x2(v.w, v.z);
        h4[idx] = wv;
    }
}

// ---------------------------------------------------------------------------
// K1: fp16 GEMM, all-f16 smem, cp.async double buffer, ldmatrix operands,
// fused per-tile argmin over codes. grid (16, 128), 256 threads (8 warps).
// ---------------------------------------------------------------------------
__global__ void __launch_bounds__(256, 2) gemm_kernel() {
    extern __shared__ __half smh[];
    __half* Ubuf = smh;                         // [2][32*SAU_H]
    __half* Abuf = smh + 2 * 32 * SAU_H;        // [2][CODT*SAC_H]

    const int tid = threadIdx.x;
    const int w = tid >> 5, lane = tid & 31;
    const int g = lane >> 2, q = lane & 3;
    const int code0 = blockIdx.x * CODT;
    const int tok0 = blockIdx.y * TOKT;
    const int b = tok0 >> 10, hw0 = tok0 & 1023;
    const __half* ub16 = g_u16 + (size_t)b * (C_ * HW_) + hw0;
    const __half* cb16 = g_cb16 + (size_t)code0 * C_;

    float acc[4][4][4];
    #pragma unroll
    for (int mt = 0; mt < 4; ++mt)
        #pragma unroll
        for (int nt = 0; nt < 4; ++nt)
            #pragma unroll
            for (int e = 0; e < 4; ++e) acc[mt][nt][e] = 0.f;

    const int a_row = lane & 15, a_col = (lane >> 4) << 3;
    const int b_k = lane & 15;

    #define STAGE_U16(kc, buf) do {                                            \
        __half* Ub_ = Ubuf + (buf) * (32 * SAU_H);                              \
        const int k0_ = (kc) * 32;                                              \
        _Pragma("unroll")                                                       \
        for (int p = 0; p < 4; ++p) {                                           \
            int id = tid + p * 256;                                             \
            int kr = id >> 5, cq = id & 31;                                     \
            uint32_t dst = (uint32_t)__cvta_generic_to_shared(                  \
                Ub_ + kr * SAU_H + cq * 8);                                     \
            CPA16(dst, ub16 + (size_t)(k0_ + kr) * HW_ + cq * 8);               \
        }                                                                       \
    } while (0)
    #define STAGE_CB16(kc, buf) do {                                            \
        __half* Ab_ = Abuf + (buf) * (CODT * SAC_H);                             \
        const int k0_ = (kc) * 32;                                               \
        int row = tid >> 2, cq = tid & 3;                                        \
        uint32_t dst = (uint32_t)__cvta_generic_to_shared(                       \
            Ab_ + row * SAC_H + cq * 8);                                         \
        CPA16(dst, cb16 + (size_t)row * C_ + k0_ + cq * 8);                      \
    } while (0)

    STAGE_U16(0, 0);
    STAGE_CB16(0, 0);
    CPA_COMMIT();
    CPA_WAIT0();
    __syncthreads();

    for (int kc = 0; kc < 8; ++kc) {
        const int buf = kc & 1;
        if (kc < 7) {
            STAGE_U16(kc + 1, buf ^ 1);
            STAGE_CB16(kc + 1, buf ^ 1);
            CPA_COMMIT();
        }

        const __half* Ub = Ubuf + buf * (32 * SAU_H);
        const __half* Ab = Abuf + buf * (CODT * SAC_H);
        const int n0 = w * 32;

        #pragma unroll
        for (int ks = 0; ks < 2; ++ks) {
            const int kb = ks * 16;
            uint32_t bf[4][2];
            #pragma unroll
            for (int nt = 0; nt < 4; ++nt) {
                uint32_t a = (uint32_t)__cvta_generic_to_shared(
                    Ub + (kb + b_k) * SAU_H + n0 + nt * 8);
                ldsm_x2t(bf[nt], a);
            }
            uint32_t af[4][4];
            #pragma unroll
            for (int mt = 0; mt < 4; ++mt) {
                uint32_t a = (uint32_t)__cvta_generic_to_shared(
                    Ab + (mt * 16 + a_row) * SAC_H + kb + a_col);
                ldsm_x4(af[mt], a);
            }
            #pragma unroll
            for (int mt = 0; mt < 4; ++mt)
                #pragma unroll
                for (int nt = 0; nt < 4; ++nt)
                    mma_f16(acc[mt][nt], af[mt], bf[nt]);
        }
        if (kc < 7) CPA_WAIT0();
        __syncthreads();
    }

    // fused argmin over codes (M)
    #pragma unroll
    for (int nt = 0; nt < 4; ++nt) {
        #pragma unroll
        for (int e = 0; e < 2; ++e) {
            float m1 = 3.4e38f, m2 = 3.4e38f;
            int i1 = 0;
            #pragma unroll
            for (int mt = 0; mt < 4; ++mt) {
                const int clo = code0 + mt * 16 + g;
                upd_min2(fmaf(-2.f, acc[mt][nt][e], __ldg(&g_cnorm[clo])),
                         clo, m1, i1, m2);
                upd_min2(fmaf(-2.f, acc[mt][nt][2 + e], __ldg(&g_cnorm[clo + 8])),
                         clo + 8, m1, i1, m2);
            }
            #pragma unroll
            for (int off = 4; off <= 16; off <<= 1) {
                float ov1 = __shfl_xor_sync(0xffffffffu, m1, off);
                int   oi1 = __shfl_xor_sync(0xffffffffu, i1, off);
                float ov2 = __shfl_xor_sync(0xffffffffu, m2, off);
                merge_min2(m1, i1, m2, ov1, oi1, ov2);
            }
            if (g == 0) {
                const int tok = tok0 + w * 32 + nt * 8 + 2 * q + e;
                g_sum[(size_t)tok * NTILE + blockIdx.x] =
                    make_float4(m1, m2, __int_as_float(i1), 0.f);
            }
        }
    }
}

// ---------------------------------------------------------------------------
// K2: reduce. TWO threads per token (8 summaries each + shfl merge).
// grid 256 blocks x 256 threads = 65536 threads.
// ---------------------------------------------------------------------------
__global__ void __launch_bounds__(256) reduce_kernel(float* __restrict__ out_idx) {
    const int id = blockIdx.x * 256 + threadIdx.x;
    const int tok = id >> 1, half = id & 1;
    const float4* sp = g_sum + (size_t)tok * NTILE + half * 8;
    float m1 = 3.4e38f, m2 = 3.4e38f;
    int i1 = 0;
    #pragma unroll
    for (int t = 0; t < 8; ++t) {
        float4 s = sp[t];
        merge_min2(m1, i1, m2, s.x, __float_as_int(s.z), s.y);
    }
    // merge with partner lane (tok pairs share a lane pair)
    float ov1 = __shfl_xor_sync(0xffffffffu, m1, 1);
    int   oi1 = __shfl_xor_sync(0xffffffffu, i1, 1);
    float ov2 = __shfl_xor_sync(0xffffffffu, m2, 1);
    merge_min2(m1, i1, m2, ov1, oi1, ov2);
    if (half) return;

    g_idx[tok] = i1;
    out_idx[tok] = (float)i1;
    const float cmax = sqrtf(__uint_as_float(g_cmax_bits)) * 1.0002f;
    const float margin = g_unorm[tok] * cmax * (1.02f / 512.f) + 2e-3f;
    if (m2 - m1 <= margin) {
        int slot = atomicAdd(&g_nambig, 1);
        g_ambig[slot] = tok;
        g_lim[slot] = m1 + margin;
    }
}

// ---------------------------------------------------------------------------
// K3: worklist rescue. Warp per entry; float4-coalesced exact fp32 dots.
// ---------------------------------------------------------------------------
__global__ void __launch_bounds__(256) rescue_kernel(const float* __restrict__ u,
                                                     const float* __restrict__ cb,
                                                     float* __restrict__ out_idx) {
    __shared__ __align__(16) float us[8][C_];
    const int wid = threadIdx.x >> 5, lane = threadIdx.x & 31;
    const int gw = blockIdx.x * 8 + wid;
    const int nwarps = gridDim.x * 8;
    const int n = g_nambig;

    const int group = lane >> 3;
    const int ks = (lane & 7) << 2;

    for (int i = gw; i < n; i += nwarps) {
        const int tok = g_ambig[i];
        const float lim = g_lim[i];
        const int b = tok >> 10, hw = tok & 1023;
        #pragma unroll
        for (int r = 0; r < 8; ++r) {
            int c = lane + r * 32;
            us[wid][c] = u[((size_t)(b * C_ + c) << 10) + hw];
        }
        __syncwarp();
        float4 uu[8];
        #pragma unroll
        for (int r = 0; r < 8; ++r)
            uu[r] = *(const float4*)&us[wid][ks + r * 32];

        const float4* sp = g_sum + (size_t)tok * NTILE;
        float best = 3.4e38f;
        int bi = KCODES;
        for (int t = 0; t < NTILE; ++t) {
            if (sp[t].x > lim) continue;
            const int cb0 = t * CODT;
            #pragma unroll 4
            for (int p = 0; p < 16; ++p) {
                const int cg = cb0 + p * 4 + group;
                const float* cp = cb + (size_t)cg * C_ + ks;
                float d = 0.f;
                #pragma unroll
                for (int r = 0; r < 8; ++r) {
                    float4 x = *(const float4*)&cp[r * 32];
                    d = fmaf(x.x, uu[r].x, d);
                    d = fmaf(x.y, uu[r].y, d);
                    d = fmaf(x.z, uu[r].z, d);
                    d = fmaf(x.w, uu[r].w, d);
                }
                d += __shfl_xor_sync(0xffffffffu, d, 1);
                d += __shfl_xor_sync(0xffffffffu, d, 2);
                d += __shfl_xor_sync(0xffffffffu, d, 4);
                const float s = fmaf(-2.f, d, __ldg(&g_cnorm[cg]));
                if (s < best || (s == best && cg < bi)) { best = s; bi = cg; }
            }
        }
        #pragma unroll
        for (int off = 16; off > 0; off >>= 1) {
            float ov = __shfl_xor_sync(0xffffffffu, best, off);
            int oi = __shfl_xor_sync(0xffffffffu, bi, off);
            if (ov < best || (ov == best && oi < bi)) { best = ov; bi = oi; }
        }
        if (lane == 0) {
            g_idx[tok] = bi;
            out_idx[tok] = (float)bi;
        }
        __syncwarp();
    }
}

// ---------------------------------------------------------------------------
// K4: outputs. copy u, gather z_q, accumulate (z_q - u)^2 per (b,c)
// ---------------------------------------------------------------------------
__global__ void __launch_bounds__(256) epilogue_kernel(const float* __restrict__ u,
                                                       float* __restrict__ out) {
    __shared__ float col[KCODES];
    __shared__ float sred[256];
    const int c = blockIdx.x;
    const int b = blockIdx.y;
    const int tid = threadIdx.x;

    ((float4*)col)[tid] = ((const float4*)(g_codebookT + c * KCODES))[tid];
    __syncthreads();

    const long base = ((long)(b * C_ + c)) << 10;
    const float* ub = u + base;
    float* ou = out + OFF_U + base;
    float* oz = out + OFF_ZT + base;
    const int* ib = g_idx + (b << 10);

    float acc = 0.f;
    #pragma unroll
    for (int j = 0; j < 4; ++j) {
        int hw = tid + (j << 8);
        int i = ib[hw];
        float z = col[i];
        float uu = ub[hw];
        ou[hw] = uu;
        oz[hw] = z;
        float d = z - uu;
        acc = fmaf(d, d, acc);
    }
    sred[tid] = acc;
    __syncthreads();
    #pragma unroll
    for (int stride = 128; stride > 0; stride >>= 1) {
        if (tid < stride) sred[tid] += sred[tid + stride];
        __syncthreads();
    }
    if (tid == 0) g_partial[b * C_ + c] = sred[0];
}

// ---------------------------------------------------------------------------
// K5: final loss
// ---------------------------------------------------------------------------
__global__ void __launch_bounds__(256) loss_kernel(float* __restrict__ out) {
    __shared__ float s[256];
    const int tid = threadIdx.x;
    float a = 0.f;
    for (int i = tid; i < B_ * C_; i += 256) a += g_partial[i];
    s[tid] = a;
    __syncthreads();
    #pragma unroll
    for (int stride = 128; stride > 0; stride >>= 1) {
        if (tid < stride) s[tid] += s[tid + stride];
        __syncthreads();
    }
    if (tid == 0)
        out[OFF_LOSS] = s[0] * (1.0f + BETA) / (float)SZ_U;
}

// ---------------------------------------------------------------------------
extern "C" void kernel_launch(void* const* d_in, const int* in_sizes, int n_in,
                              void* d_out, int out_size) {
    const float* u  = (const float*)d_in[0];
    const float* cb = (const float*)d_in[1];
    float* out = (float*)d_out;

    static bool attr_done = false;
    if (!attr_done) {
        cudaFuncSetAttribute(gemm_kernel,
                             cudaFuncAttributeMaxDynamicSharedMemorySize,
                             GEMM_SMEM);
        attr_done = true;
    }

    prep_kernel<<<KCODES, 256>>>(cb);
    prep_u16_kernel<<<1024, 256>>>(u);
    unorm_kernel<<<dim3(8, B_), 128>>>(u);
    gemm_kernel<<<dim3(NTILE, NTOK / TOKT), 256, GEMM_SMEM>>>();
    reduce_kernel<<<NTOK * 2 / 256, 256>>>(out + OFF_IDX);
    rescue_kernel<<<512, 256>>>(u, cb, out + OFF_IDX);
    epilogue_kernel<<<dim3(C_, B_), 256>>>(u, out);
    loss_kernel<<<1, 256>>>(out);
}

// round 17
// speedup vs baseline: 1.1313x; 1.0658x over previous
#include <cuda_runtime.h>
#include <cuda_bf16.h>
#include <cuda_fp16.h>
#include <cstdint>

// Problem constants
#define B_      32
#define C_      256
#define HW_     1024
#define NTOK    32768
#define KCODES  1024
#define BETA    0.25f

// Output layout (concatenated float32): u, z_train, vq_loss, indices
#define SZ_U    8388608
#define OFF_U   0
#define OFF_ZT  8388608
#define OFF_LOSS 16777216
#define OFF_IDX  16777217

// GEMM tiling: CTA = 64 codes (MMA-M) x 256 tokens (MMA-N), K=256 in 4x64
#define TOKT 256
#define CODT 64
#define NTILE (KCODES / CODT)   // 16
#define KCH   64                // k per chunk
#define NCHUNK (C_ / KCH)       // 4
#define SAU_H 264       // u16 smem stride (halves): 33x16B, 33%8==1 -> ldsm ok
#define SAC_H 72        // cb16 smem stride (halves): 9x16B, 9%8==1 -> ldsm ok
#define GEMM_SMEM (2 * KCH * SAU_H * 2 + 2 * CODT * SAC_H * 2)   // 153600? no:
// 2*64*264*2 = 135168 ; 2*64*72*2 = 18432 ; total 153600 TOO BIG for 2 CTA.
// -> use single-K-chunk-64 with u tile [64][SAU_H]: 64*264*2=33792/stage.
// 2 stages u = 67584 + 2 stages cb = 18432 -> 86016 B. (defined below)
#undef GEMM_SMEM
#define GEMM_SMEM (2 * KCH * SAU_H * 2 + 2 * CODT * SAC_H * 2)

// Device scratch
__device__ float g_codebookT[C_ * KCODES];     // [c][code]
__device__ float g_cnorm[KCODES];
__device__ unsigned g_cmax_bits;
__device__ float g_unorm[NTOK];
__device__ int   g_idx[NTOK];
__device__ float g_partial[B_ * C_];
__device__ __align__(16) __half g_u16[NTOK * C_];    // [b][c][hw] f16, 16 MB
__device__ __align__(16) __half g_cb16[KCODES * C_]; // [code][k] f16
__device__ __align__(16) float4 g_sum[NTOK * NTILE]; // {m1, m2, idx_bits, pad}
__device__ int   g_nambig;
__device__ int   g_ambig[NTOK];
__device__ float g_lim[NTOK];

// ---------------------------------------------------------------------------
__device__ __forceinline__ uint32_t pack_f16x2(float hi, float lo) {
    uint32_t d;
    asm("cvt.rn.f16x2.f32 %0, %1, %2;" : "=r"(d) : "f"(hi), "f"(lo));
    return d;
}

#define CPA16(dst, src) \
    asm volatile("cp.async.cg.shared.global [%0], [%1], 16;" :: "r"(dst), "l"(src))
#define CPA_COMMIT() asm volatile("cp.async.commit_group;" ::: "memory")
#define CPA_WAIT0()  asm volatile("cp.async.wait_group 0;" ::: "memory")

__device__ __forceinline__ void ldsm_x4(uint32_t* r, uint32_t a) {
    asm volatile("ldmatrix.sync.aligned.m8n8.x4.shared.b16 {%0,%1,%2,%3}, [%4];"
        : "=r"(r[0]), "=r"(r[1]), "=r"(r[2]), "=r"(r[3]) : "r"(a));
}
__device__ __forceinline__ void ldsm_x2t(uint32_t* r, uint32_t a) {
    asm volatile("ldmatrix.sync.aligned.m8n8.x2.trans.shared.b16 {%0,%1}, [%2];"
        : "=r"(r[0]), "=r"(r[1]) : "r"(a));
}

__device__ __forceinline__ void mma_f16(float* c, const uint32_t* a,
                                        const uint32_t* b) {
    asm volatile(
        "mma.sync.aligned.m16n8k16.row.col.f32.f16.f16.f32 "
        "{%0,%1,%2,%3}, {%4,%5,%6,%7}, {%8,%9}, {%0,%1,%2,%3};"
        : "+f"(c[0]), "+f"(c[1]), "+f"(c[2]), "+f"(c[3])
        : "r"(a[0]), "r"(a[1]), "r"(a[2]), "r"(a[3]), "r"(b[0]), "r"(b[1]));
}

__device__ __forceinline__ void upd_min2(float v, int i, float& m1, int& i1,
                                         float& m2) {
    if (v < m1) { m2 = m1; m1 = v; i1 = i; }
    else if (v < m2) { m2 = v; }
}

__device__ __forceinline__ void merge_min2(float& v1, int& i1, float& v2,
                                           float ov1, int oi1, float ov2) {
    if (ov1 < v1 || (ov1 == v1 && oi1 < i1)) {
        v2 = fminf(v1, ov2);
        v1 = ov1; i1 = oi1;
    } else {
        v2 = fminf(v2, ov1);
    }
}

// ---------------------------------------------------------------------------
// K0: codebook transpose + |c|^2 + cmax + f16 copy + zero ambig counter
// ---------------------------------------------------------------------------
__global__ void __launch_bounds__(256) prep_kernel(const float* __restrict__ cb) {
    __shared__ float s[256];
    int k = blockIdx.x;
    int c = threadIdx.x;
    if (k == 0 && c == 0) g_nambig = 0;
    float v = cb[k * C_ + c];
    g_codebookT[c * KCODES + k] = v;
    g_cb16[k * C_ + c] = __float2half_rn(v);
    s[c] = v * v;
    __syncthreads();
    #pragma unroll
    for (int stride = 128; stride > 0; stride >>= 1) {
        if (c < stride) s[c] += s[c + stride];
        __syncthreads();
    }
    if (c == 0) {
        g_cnorm[k] = s[0];
        atomicMax(&g_cmax_bits, __float_as_uint(s[0]));
    }
}

// K0b: u -> f16, coalesced.
__global__ void __launch_bounds__(256) prep_u16_kernel(const float* __restrict__ u) {
    const float4* u4 = (const float4*)u;
    uint2* h4 = (uint2*)g_u16;
    const size_t base = (size_t)blockIdx.x * 2048 + threadIdx.x;
    #pragma unroll
    for (int p = 0; p < 8; ++p) {
        const size_t idx = base + p * 256;
        float4 v = u4[idx];
        uint2 wv;
        wv.x = pack_f16x2(v.y, v.x);
        wv.y = pack_f16x2(v.w, v.z);
        h4[idx] = wv;
    }
}

// K0c: per-token ||u|| upper bound from g_u16 (f16 rel err <= 2^-11;
// inflate 1.003 to keep a rigorous bound).
__global__ void __launch_bounds__(128) unorm_kernel() {
    const int b = blockIdx.y;
    const int hw = blockIdx.x * 128 + threadIdx.x;
    const __half* up = g_u16 + (size_t)b * (C_ * HW_) + hw;
    float acc = 0.f;
    #pragma unroll 8
    for (int c = 0; c < C_; ++c) {
        float v = __half2float(up[(size_t)c * HW_]);
        acc = fmaf(v, v, acc);
    }
    g_unorm[(b << 10) + hw] = sqrtf(acc) * 1.003f;
}

// ---------------------------------------------------------------------------
// K1: fp16 GEMM, all-f16 smem, cp.async double buffer (K-chunk 64, 4 chunks),
// ldmatrix operands, fused per-tile argmin over codes.
// grid (16, 128), 256 threads (8 warps).
// ---------------------------------------------------------------------------
__global__ void __launch_bounds__(256, 2) gemm_kernel() {
    extern __shared__ __half smh[];
    __half* Ubuf = smh;                         // [2][KCH*SAU_H]
    __half* Abuf = smh + 2 * KCH * SAU_H;       // [2][CODT*SAC_H]

    const int tid = threadIdx.x;
    const int w = tid >> 5, lane = tid & 31;
    const int g = lane >> 2, q = lane & 3;
    const int code0 = blockIdx.x * CODT;
    const int tok0 = blockIdx.y * TOKT;
    const int b = tok0 >> 10, hw0 = tok0 & 1023;
    const __half* ub16 = g_u16 + (size_t)b * (C_ * HW_) + hw0;
    const __half* cb16 = g_cb16 + (size_t)code0 * C_;

    float acc[4][4][4];
    #pragma unroll
    for (int mt = 0; mt < 4; ++mt)
        #pragma unroll
        for (int nt = 0; nt < 4; ++nt)
            #pragma unroll
            for (int e = 0; e < 4; ++e) acc[mt][nt][e] = 0.f;

    const int a_row = lane & 15, a_col = (lane >> 4) << 3;
    const int b_k = lane & 15;

    // staging: U chunk = 64 k-rows x 256 tokens f16 = 32 KB -> 8 cp.async/thr
    //          CB chunk = 64 codes x 64 k f16 = 8 KB -> 2 cp.async/thr
    #define STAGE_U16(kc, buf) do {                                            \
        __half* Ub_ = Ubuf + (buf) * (KCH * SAU_H);                             \
        const int k0_ = (kc) * KCH;                                             \
        _Pragma("unroll")                                                       \
        for (int p = 0; p < 8; ++p) {                                           \
            int id = tid + p * 256;                                             \
            int kr = id >> 5, cq = id & 31;                                     \
            uint32_t dst = (uint32_t)__cvta_generic_to_shared(                  \
                Ub_ + kr * SAU_H + cq * 8);                                     \
            CPA16(dst, ub16 + (size_t)(k0_ + kr) * HW_ + cq * 8);               \
        }                                                                       \
    } while (0)
    #define STAGE_CB16(kc, buf) do {                                            \
        __half* Ab_ = Abuf + (buf) * (CODT * SAC_H);                             \
        const int k0_ = (kc) * KCH;                                              \
        _Pragma("unroll")                                                        \
        for (int p = 0; p < 2; ++p) {                                            \
            int id = tid + p * 256;                                              \
            int row = id >> 3, cq = id & 7;                                      \
            uint32_t dst = (uint32_t)__cvta_generic_to_shared(                   \
                Ab_ + row * SAC_H + cq * 8);                                      \
            CPA16(dst, cb16 + (size_t)row * C_ + k0_ + cq * 8);                   \
        }                                                                         \
    } while (0)

    STAGE_U16(0, 0);
    STAGE_CB16(0, 0);
    CPA_COMMIT();
    CPA_WAIT0();
    __syncthreads();

    for (int kc = 0; kc < NCHUNK; ++kc) {
        const int buf = kc & 1;
        if (kc < NCHUNK - 1) {
            STAGE_U16(kc + 1, buf ^ 1);
            STAGE_CB16(kc + 1, buf ^ 1);
            CPA_COMMIT();
        }

        const __half* Ub = Ubuf + buf * (KCH * SAU_H);
        const __half* Ab = Abuf + buf * (CODT * SAC_H);
        const int n0 = w * 32;

        #pragma unroll
        for (int ks = 0; ks < 4; ++ks) {
            const int kb = ks * 16;
            uint32_t bf[4][2];
            #pragma unroll
            for (int nt = 0; nt < 4; ++nt) {
                uint32_t a = (uint32_t)__cvta_generic_to_shared(
                    Ub + (kb + b_k) * SAU_H + n0 + nt * 8);
                ldsm_x2t(bf[nt], a);
            }
            uint32_t af[4][4];
            #pragma unroll
            for (int mt = 0; mt < 4; ++mt) {
                uint32_t a = (uint32_t)__cvta_generic_to_shared(
                    Ab + (mt * 16 + a_row) * SAC_H + kb + a_col);
                ldsm_x4(af[mt], a);
            }
            #pragma unroll
            for (int mt = 0; mt < 4; ++mt)
                #pragma unroll
                for (int nt = 0; nt < 4; ++nt)
                    mma_f16(acc[mt][nt], af[mt], bf[nt]);
        }
        if (kc < NCHUNK - 1) CPA_WAIT0();
        __syncthreads();
    }

    // fused argmin over codes (M)
    #pragma unroll
    for (int nt = 0; nt < 4; ++nt) {
        #pragma unroll
        for (int e = 0; e < 2; ++e) {
            float m1 = 3.4e38f, m2 = 3.4e38f;
            int i1 = 0;
            #pragma unroll
            for (int mt = 0; mt < 4; ++mt) {
                const int clo = code0 + mt * 16 + g;
                upd_min2(fmaf(-2.f, acc[mt][nt][e], __ldg(&g_cnorm[clo])),
                         clo, m1, i1, m2);
                upd_min2(fmaf(-2.f, acc[mt][nt][2 + e], __ldg(&g_cnorm[clo + 8])),
                         clo + 8, m1, i1, m2);
            }
            #pragma unroll
            for (int off = 4; off <= 16; off <<= 1) {
                float ov1 = __shfl_xor_sync(0xffffffffu, m1, off);
                int   oi1 = __shfl_xor_sync(0xffffffffu, i1, off);
                float ov2 = __shfl_xor_sync(0xffffffffu, m2, off);
                merge_min2(m1, i1, m2, ov1, oi1, ov2);
            }
            if (g == 0) {
                const int tok = tok0 + w * 32 + nt * 8 + 2 * q + e;
                g_sum[(size_t)tok * NTILE + blockIdx.x] =
                    make_float4(m1, m2, __int_as_float(i1), 0.f);
            }
        }
    }
}

// ---------------------------------------------------------------------------
// K2: reduce. TWO threads per token (8 summaries each + shfl merge).
// ---------------------------------------------------------------------------
__global__ void __launch_bounds__(256) reduce_kernel(float* __restrict__ out_idx) {
    const int id = blockIdx.x * 256 + threadIdx.x;
    const int tok = id >> 1, half = id & 1;
    const float4* sp = g_sum + (size_t)tok * NTILE + half * 8;
    float m1 = 3.4e38f, m2 = 3.4e38f;
    int i1 = 0;
    #pragma unroll
    for (int t = 0; t < 8; ++t) {
        float4 s = sp[t];
        merge_min2(m1, i1, m2, s.x, __float_as_int(s.z), s.y);
    }
    float ov1 = __shfl_xor_sync(0xffffffffu, m1, 1);
    int   oi1 = __shfl_xor_sync(0xffffffffu, i1, 1);
    float ov2 = __shfl_xor_sync(0xffffffffu, m2, 1);
    merge_min2(m1, i1, m2, ov1, oi1, ov2);
    if (half) return;

    g_idx[tok] = i1;
    out_idx[tok] = (float)i1;
    const float cmax = sqrtf(__uint_as_float(g_cmax_bits)) * 1.0002f;
    const float margin = g_unorm[tok] * cmax * (1.02f / 512.f) + 2e-3f;
    if (m2 - m1 <= margin) {
        int slot = atomicAdd(&g_nambig, 1);
        g_ambig[slot] = tok;
        g_lim[slot] = m1 + margin;
    }
}

// ---------------------------------------------------------------------------
// K3: worklist rescue. Warp per entry; float4-coalesced exact fp32 dots.
// ---------------------------------------------------------------------------
__global__ void __launch_bounds__(256) rescue_kernel(const float* __restrict__ u,
                                                     const float* __restrict__ cb,
                                                     float* __restrict__ out_idx) {
    __shared__ __align__(16) float us[8][C_];
    const int wid = threadIdx.x >> 5, lane = threadIdx.x & 31;
    const int gw = blockIdx.x * 8 + wid;
    const int nwarps = gridDim.x * 8;
    const int n = g_nambig;

    const int group = lane >> 3;
    const int ks = (lane & 7) << 2;

    for (int i = gw; i < n; i += nwarps) {
        const int tok = g_ambig[i];
        const float lim = g_lim[i];
        const int b = tok >> 10, hw = tok & 1023;
        #pragma unroll
        for (int r = 0; r < 8; ++r) {
            int c = lane + r * 32;
            us[wid][c] = u[((size_t)(b * C_ + c) << 10) + hw];
        }
        __syncwarp();
        float4 uu[8];
        #pragma unroll
        for (int r = 0; r < 8; ++r)
            uu[r] = *(const float4*)&us[wid][ks + r * 32];

        const float4* sp = g_sum + (size_t)tok * NTILE;
        float best = 3.4e38f;
        int bi = KCODES;
        for (int t = 0; t < NTILE; ++t) {
            if (sp[t].x > lim) continue;
            const int cb0 = t * CODT;
            #pragma unroll 4
            for (int p = 0; p < 16; ++p) {
                const int cg = cb0 + p * 4 + group;
                const float* cp = cb + (size_t)cg * C_ + ks;
                float d = 0.f;
                #pragma unroll
                for (int r = 0; r < 8; ++r) {
                    float4 x = *(const float4*)&cp[r * 32];
                    d = fmaf(x.x, uu[r].x, d);
                    d = fmaf(x.y, uu[r].y, d);
                    d = fmaf(x.z, uu[r].z, d);
                    d = fmaf(x.w, uu[r].w, d);
                }
                d += __shfl_xor_sync(0xffffffffu, d, 1);
                d += __shfl_xor_sync(0xffffffffu, d, 2);
                d += __shfl_xor_sync(0xffffffffu, d, 4);
                const float s = fmaf(-2.f, d, __ldg(&g_cnorm[cg]));
                if (s < best || (s == best && cg < bi)) { best = s; bi = cg; }
            }
        }
        #pragma unroll
        for (int off = 16; off > 0; off >>= 1) {
            float ov = __shfl_xor_sync(0xffffffffu, best, off);
            int oi = __shfl_xor_sync(0xffffffffu, bi, off);
            if (ov < best || (ov == best && oi < bi)) { best = ov; bi = oi; }
        }
        if (lane == 0) {
            g_idx[tok] = bi;
            out_idx[tok] = (float)bi;
        }
        __syncwarp();
    }
}

// ---------------------------------------------------------------------------
// K4: outputs. copy u, gather z_q, accumulate (z_q - u)^2 per (b,c)
// ---------------------------------------------------------------------------
__global__ void __launch_bounds__(256) epilogue_kernel(const float* __restrict__ u,
                                                       float* __restrict__ out) {
    __shared__ float col[KCODES];
    __shared__ float sred[256];
    const int c = blockIdx.x;
    const int b = blockIdx.y;
    const int tid = threadIdx.x;

    ((float4*)col)[tid] = ((const float4*)(g_codebookT + c * KCODES))[tid];
    __syncthreads();

    const long base = ((long)(b * C_ + c)) << 10;
    const float* ub = u + base;
    float* ou = out + OFF_U + base;
    float* oz = out + OFF_ZT + base;
    const int* ib = g_idx + (b << 10);

    float acc = 0.f;
    #pragma unroll
    for (int j = 0; j < 4; ++j) {
        int hw = tid + (j << 8);
        int i = ib[hw];
        float z = col[i];
        float uu = ub[hw];
        ou[hw] = uu;
        oz[hw] = z;
        float d = z - uu;
        acc = fmaf(d, d, acc);
    }
    sred[tid] = acc;
    __syncthreads();
    #pragma unroll
    for (int stride = 128; stride > 0; stride >>= 1) {
        if (tid < stride) sred[tid] += sred[tid + stride];
        __syncthreads();
    }
    if (tid == 0) g_partial[b * C_ + c] = sred[0];
}

// ---------------------------------------------------------------------------
// K5: final loss
// ---------------------------------------------------------------------------
__global__ void __launch_bounds__(256) loss_kernel(float* __restrict__ out) {
    __shared__ float s[256];
    const int tid = threadIdx.x;
    float a = 0.f;
    for (int i = tid; i < B_ * C_; i += 256) a += g_partial[i];
    s[tid] = a;
    __syncthreads();
    #pragma unroll
    for (int stride = 128; stride > 0; stride >>= 1) {
        if (tid < stride) s[tid] += s[tid + stride];
        __syncthreads();
    }
    if (tid == 0)
        out[OFF_LOSS] = s[0] * (1.0f + BETA) / (float)SZ_U;
}

// ---------------------------------------------------------------------------
extern "C" void kernel_launch(void* const* d_in, const int* in_sizes, int n_in,
                              void* d_out, int out_size) {
    const float* u  = (const float*)d_in[0];
    const float* cb = (const float*)d_in[1];
    float* out = (float*)d_out;

    static bool attr_done = false;
    if (!attr_done) {
        cudaFuncSetAttribute(gemm_kernel,
                             cudaFuncAttributeMaxDynamicSharedMemorySize,
                             GEMM_SMEM);
        attr_done = true;
    }

    prep_kernel<<<KCODES, 256>>>(cb);
    prep_u16_kernel<<<1024, 256>>>(u);
    unorm_kernel<<<dim3(8, B_), 128>>>();
    gemm_kernel<<<dim3(NTILE, NTOK / TOKT), 256, GEMM_SMEM>>>();
    reduce_kernel<<<NTOK * 2 / 256, 256>>>(out + OFF_IDX);
    rescue_kernel<<<512, 256>>>(u, cb, out + OFF_IDX);
    epilogue_kernel<<<dim3(C_, B_), 256>>>(u, out);
    loss_kernel<<<1, 256>>>(out);
}